// round 6
// baseline (speedup 1.0000x reference)
#include <cuda_runtime.h>
#include <cstdint>

#define DIM 128
#define HID 64
#define MAX_TISSUE 4096
#define TILE 64
#define SXS 132  // padded float stride, X tile
#define SWS 132  // padded float stride, Wc tile (tf32 bits)

// scratch: projected tissue keys (+ both biases folded in)
__device__ float g_tkb[MAX_TISSUE * HID];

// ---------------------------------------------------------------------------
// Kernel A: tkb[t][h] = bt[h] + bc[h] + sum_d Wt[h][d] * tissue[t][d]
// ---------------------------------------------------------------------------
__global__ void tissue_proj_kernel(const float* __restrict__ tissue,
                                   const float* __restrict__ Wt,
                                   const float* __restrict__ bt,
                                   const float* __restrict__ bc,
                                   int n_tissue) {
    __shared__ float st[16][DIM];
    __shared__ float swt[HID][DIM + 4];
    int tid = threadIdx.x;
    int t0 = blockIdx.x * 16;

    for (int i = tid; i < HID * (DIM / 4); i += 256) {
        int h = i >> 5, c = i & 31;
        float4 v = ((const float4*)Wt)[h * 32 + c];
        *(float4*)&swt[h][c * 4] = v;
    }
    for (int i = tid; i < 16 * 32; i += 256) {
        int r = i >> 5, c = i & 31;
        float4 v = make_float4(0.f, 0.f, 0.f, 0.f);
        if (t0 + r < n_tissue) v = ((const float4*)tissue)[(size_t)(t0 + r) * 32 + c];
        *(float4*)&st[r][c * 4] = v;
    }
    __syncthreads();

    #pragma unroll
    for (int j = 0; j < 4; j++) {
        int o = tid + j * 256;
        int tl = o >> 6, h = o & 63;
        if (t0 + tl >= n_tissue) continue;
        float acc = bt[h] + bc[h];
        #pragma unroll 8
        for (int c = 0; c < 32; c++) {
            float4 w = *(const float4*)&swt[h][c * 4];
            float4 x = *(const float4*)&st[tl][c * 4];
            acc += w.x * x.x + w.y * x.y + w.z * x.z + w.w * x.w;
        }
        g_tkb[(size_t)(t0 + tl) * HID + h] = acc;
    }
}

// ---------------------------------------------------------------------------
__device__ __forceinline__ unsigned f2tf32(float x) {
    unsigned r;
    asm("cvt.rna.tf32.f32 %0, %1;" : "=r"(r) : "f"(x));
    return r;
}
__device__ __forceinline__ float tanh_ap(float x) {
    float y;
    asm("tanh.approx.f32 %0, %1;" : "=f"(y) : "f"(x));
    return y;
}
__device__ __forceinline__ void cp_async16(void* sdst, const void* gsrc, bool pred) {
    unsigned s = (unsigned)__cvta_generic_to_shared(sdst);
    int sz = pred ? 16 : 0;
    asm volatile("cp.async.cg.shared.global [%0], [%1], 16, %2;\n"
                 :: "r"(s), "l"(gsrc), "r"(sz));
}
__device__ __forceinline__ void cp_async4(void* sdst, const void* gsrc, bool pred) {
    unsigned s = (unsigned)__cvta_generic_to_shared(sdst);
    int sz = pred ? 4 : 0;
    asm volatile("cp.async.ca.shared.global [%0], [%1], 4, %2;\n"
                 :: "r"(s), "l"(gsrc), "r"(sz));
}
__device__ __forceinline__ void cp_commit() {
    asm volatile("cp.async.commit_group;\n" ::: "memory");
}
__device__ __forceinline__ void cp_wait1() {
    asm volatile("cp.async.wait_group 1;\n" ::: "memory");
}
__device__ __forceinline__ void ldm_x4(unsigned* r, unsigned saddr) {
    asm volatile("ldmatrix.sync.aligned.m8n8.x4.shared.b16 {%0,%1,%2,%3}, [%4];"
                 : "=r"(r[0]), "=r"(r[1]), "=r"(r[2]), "=r"(r[3])
                 : "r"(saddr));
}
__device__ __forceinline__ void prefetch_l1(const void* p) {
    asm volatile("prefetch.global.L1 [%0];" :: "l"(p));
}

extern __shared__ float smem[];

// ---------------------------------------------------------------------------
// Kernel B: persistent, double-buffered; 64-row tiles; 2 CTAs/SM; LDSM feeds
// Warp grid: 4 m-tiles (16 rows) x 2 n-halves (32 cols)
// ---------------------------------------------------------------------------
__global__ __launch_bounds__(256, 2)
void fuse_kernel(const float* __restrict__ cellf,
                 const float* __restrict__ tissuef,
                 const int* __restrict__ c2t,
                 const float* __restrict__ Wc,
                 const float* __restrict__ attnw,
                 float* __restrict__ out,
                 int n_cell, int ntiles) {
    float*    sx    = smem;                              // 2 buffers, 64*132
    unsigned* swc   = (unsigned*)(sx + 2 * TILE * SXS);  // 64*132 tf32 bits
    int*      stid  = (int*)(swc + 64 * SWS);            // 2 buffers, 64 each
    float*    spart = (float*)(stid + 2 * TILE);         // 2 * 64 partials
    float*    sgate = spart + 2 * TILE;                  // 64
    float*    sattn = sgate + TILE;                      // 64

    int tid = threadIdx.x;

    // ---- one-time staging: Wc (tf32, RN) + attn weights ----
    for (int i = tid; i < 64 * 32; i += 256) {
        int r = i >> 5, c = i & 31;
        float4 v = ((const float4*)Wc)[r * 32 + c];
        uint4 w;
        w.x = f2tf32(v.x); w.y = f2tf32(v.y); w.z = f2tf32(v.z); w.w = f2tf32(v.w);
        *(uint4*)&swc[r * SWS + c * 4] = w;
    }
    if (tid < 64) sattn[tid] = attnw[tid];

    int wid = tid >> 5, lane = tid & 31;
    int gid = lane >> 2, tig = lane & 3;
    int wm = wid >> 1, wn = wid & 1;     // 4 x 2 warp grid
    int m0 = wm * 16;
    int rlo = m0 + gid, rhi = m0 + gid + 8;
    int h0 = wn * 32;

    // ldmatrix lane addressing: mat = lane/8, row-in-mat = lane%8
    int lml = lane & 7, lmm = lane >> 3;
    unsigned sx_u  = (unsigned)__cvta_generic_to_shared(sx);
    unsigned swc_u = (unsigned)__cvta_generic_to_shared(swc);
    // A mats: {rows m0..+7 | m0+8..+15} x {cols +0..3 | +4..7}
    unsigned a_off = ((unsigned)((m0 + (lmm & 1) * 8 + lml) * SXS + (lmm >> 1) * 4)) * 4u;
    // B mats: rows h0+nt*8+l, k-col groups {0,4,8,12} by mat
    unsigned b_off = swc_u + ((unsigned)((h0 + lml) * SWS + lmm * 4)) * 4u;

    // ---- tile issue helper ----
    auto issue_tile = [&](int t, int buf) {
        float* dst = sx + buf * TILE * SXS;
        int base = t * TILE;
        #pragma unroll
        for (int j = 0; j < 8; j++) {
            int i = tid + j * 256;
            int r = i >> 5, c = i & 31;
            int row = base + r;
            bool ok = row < n_cell;
            int rowc = ok ? row : (n_cell - 1);
            cp_async16(&dst[r * SXS + c * 4],
                       cellf + (size_t)rowc * DIM + c * 4, ok);
        }
        if (tid < TILE) {
            int row = base + tid;
            bool ok = row < n_cell;
            int rowc = ok ? row : 0;
            cp_async4(&stid[buf * TILE + tid], c2t + rowc, ok);
        }
    };

    int t0 = blockIdx.x;
    if (t0 < ntiles) issue_tile(t0, 0);
    cp_commit();

    int it = 0;
    for (int t = t0; t < ntiles; t += gridDim.x, it++) {
        int buf = it & 1;
        int tn = t + gridDim.x;
        if (tn < ntiles) issue_tile(tn, buf ^ 1);
        cp_commit();
        cp_wait1();            // tile t resident
        __syncthreads();       // covers one-time Wc staging on iter 0

        int base = t * TILE;
        float* bx = sx + buf * TILE * SXS;
        int* bt_ = stid + buf * TILE;
        unsigned abase = sx_u + (unsigned)(buf * TILE * SXS) * 4u + a_off;

        // ---- init accumulators from gathered tissue keys (bias pre-folded) ----
        float acc[4][4];
        {
            int tlo = bt_[rlo] & (MAX_TISSUE - 1);
            int thi = bt_[rhi] & (MAX_TISSUE - 1);
            const float2* klo = (const float2*)&g_tkb[(size_t)tlo * HID];
            const float2* khi = (const float2*)&g_tkb[(size_t)thi * HID];
            #pragma unroll
            for (int nt = 0; nt < 4; nt++) {
                float2 a = klo[wn * 16 + nt * 4 + tig];
                float2 b = khi[wn * 16 + nt * 4 + tig];
                acc[nt][0] = a.x; acc[nt][1] = a.y;
                acc[nt][2] = b.x; acc[nt][3] = b.y;
            }
        }

        // ---- prefetch epilogue tissue rows into L1 (overlaps with mma) ----
        #pragma unroll
        for (int j = 0; j < 8; j++) {
            int r = wid + j * 8;
            int tt = bt_[r];
            prefetch_l1(tissuef + (size_t)tt * DIM + lane * 4);
        }

        // ---- Q += X @ Wc^T via ldmatrix + mma.sync m16n8k8 tf32 ----
        #pragma unroll
        for (int p = 0; p < 8; p++) {
            unsigned a0[4], a1[4];
            ldm_x4(a0, abase + (unsigned)(p * 64));        // kk = 2p
            ldm_x4(a1, abase + (unsigned)(p * 64 + 32));   // kk = 2p+1
            #pragma unroll
            for (int nt = 0; nt < 4; nt++) {
                unsigned b[4];  // b[0],b[1]: kk=2p ; b[2],b[3]: kk=2p+1
                ldm_x4(b, b_off + (unsigned)(nt * 8 * SWS) * 4u + (unsigned)(p * 64));
                asm volatile(
                    "mma.sync.aligned.m16n8k8.row.col.f32.tf32.tf32.f32 "
                    "{%0,%1,%2,%3}, {%4,%5,%6,%7}, {%8,%9}, {%0,%1,%2,%3};\n"
                    : "+f"(acc[nt][0]), "+f"(acc[nt][1]),
                      "+f"(acc[nt][2]), "+f"(acc[nt][3])
                    : "r"(a0[0]), "r"(a0[1]), "r"(a0[2]), "r"(a0[3]),
                      "r"(b[0]), "r"(b[1]));
                asm volatile(
                    "mma.sync.aligned.m16n8k8.row.col.f32.tf32.tf32.f32 "
                    "{%0,%1,%2,%3}, {%4,%5,%6,%7}, {%8,%9}, {%0,%1,%2,%3};\n"
                    : "+f"(acc[nt][0]), "+f"(acc[nt][1]),
                      "+f"(acc[nt][2]), "+f"(acc[nt][3])
                    : "r"(a1[0]), "r"(a1[1]), "r"(a1[2]), "r"(a1[3]),
                      "r"(b[2]), "r"(b[3]));
            }
        }

        // ---- partial score = attn . tanh(acc) over this warp's 32 cols ----
        float p0 = 0.f, p1 = 0.f;
        #pragma unroll
        for (int nt = 0; nt < 4; nt++) {
            float aw0 = sattn[h0 + nt * 8 + tig * 2];
            float aw1 = sattn[h0 + nt * 8 + tig * 2 + 1];
            p0 += aw0 * tanh_ap(acc[nt][0]) + aw1 * tanh_ap(acc[nt][1]);
            p1 += aw0 * tanh_ap(acc[nt][2]) + aw1 * tanh_ap(acc[nt][3]);
        }
        p0 += __shfl_xor_sync(0xffffffffu, p0, 1);
        p0 += __shfl_xor_sync(0xffffffffu, p0, 2);
        p1 += __shfl_xor_sync(0xffffffffu, p1, 1);
        p1 += __shfl_xor_sync(0xffffffffu, p1, 2);
        if (tig == 0) {
            spart[wn * TILE + rlo] = p0;
            spart[wn * TILE + rhi] = p1;
        }
        __syncthreads();

        // ---- combine partials, gate = sigmoid ----
        if (tid < TILE) {
            float s = spart[tid] + spart[TILE + tid];
            sgate[tid] = __fdividef(1.f, 1.f + __expf(-s));
        }
        __syncthreads();

        // ---- out = x + tissue[t]*gate ----
        #pragma unroll
        for (int j = 0; j < 8; j++) {
            int i = tid + j * 256;
            int r = i >> 5, c = i & 31;
            int row = base + r;
            if (row >= n_cell) continue;
            float4 xv = *(const float4*)&bx[r * SXS + c * 4];
            float g = sgate[r];
            int tt = bt_[r];
            float4 tv = ((const float4*)tissuef)[(size_t)tt * 32 + c];
            float4 o;
            o.x = fmaf(tv.x, g, xv.x);
            o.y = fmaf(tv.y, g, xv.y);
            o.z = fmaf(tv.z, g, xv.z);
            o.w = fmaf(tv.w, g, xv.w);
            ((float4*)out)[(size_t)row * 32 + c] = o;
        }
        __syncthreads();   // buffer reusable next-next iteration
    }
}

// ---------------------------------------------------------------------------
extern "C" void kernel_launch(void* const* d_in, const int* in_sizes, int n_in,
                              void* d_out, int out_size) {
    const float* cellf   = (const float*)d_in[0];
    const float* tissuef = (const float*)d_in[1];
    const int*   c2t     = (const int*)d_in[2];
    const float* Wt      = (const float*)d_in[3];
    const float* bt      = (const float*)d_in[4];
    const float* Wc      = (const float*)d_in[5];
    const float* bc      = (const float*)d_in[6];
    const float* attnw   = (const float*)d_in[7];
    float* out = (float*)d_out;

    int n_cell   = in_sizes[0] / DIM;
    int n_tissue = in_sizes[1] / DIM;
    int ntiles   = (n_cell + TILE - 1) / TILE;

    tissue_proj_kernel<<<(n_tissue + 15) / 16, 256>>>(tissuef, Wt, bt, bc, n_tissue);

    int dev = 0, sms = 148;
    cudaGetDevice(&dev);
    cudaDeviceGetAttribute(&sms, cudaDevAttrMultiProcessorCount, dev);

    size_t shmem_bytes =
        (size_t)(2 * TILE * SXS + 64 * SWS) * 4
        + (2 * TILE) * 4
        + (2 * TILE) * 4
        + TILE * 4
        + 64 * 4;
    cudaFuncSetAttribute(fuse_kernel,
                         cudaFuncAttributeMaxDynamicSharedMemorySize,
                         (int)shmem_bytes);
    int grid = 2 * sms;
    if (grid > ntiles) grid = ntiles;
    fuse_kernel<<<grid, 256, shmem_bytes>>>(cellf, tissuef, c2t, Wc, attnw,
                                            out, n_cell, ntiles);
}

// round 7
// speedup vs baseline: 1.0198x; 1.0198x over previous
#include <cuda_runtime.h>
#include <cstdint>

#define DIM 128
#define HID 64
#define MAX_TISSUE 4096
#define TILE 32
#define SXS 132  // padded float stride, X tile
#define SWS 132  // padded float stride, Wc tile (tf32 bits)

// scratch: projected tissue keys (+ both biases folded in)
__device__ float g_tkb[MAX_TISSUE * HID];

// ---------------------------------------------------------------------------
// Kernel A: tkb[t][h] = bt[h] + bc[h] + sum_d Wt[h][d] * tissue[t][d]
// ---------------------------------------------------------------------------
__global__ void tissue_proj_kernel(const float* __restrict__ tissue,
                                   const float* __restrict__ Wt,
                                   const float* __restrict__ bt,
                                   const float* __restrict__ bc,
                                   int n_tissue) {
    __shared__ float st[16][DIM];
    __shared__ float swt[HID][DIM + 4];
    int tid = threadIdx.x;
    int t0 = blockIdx.x * 16;

    for (int i = tid; i < HID * (DIM / 4); i += 256) {
        int h = i >> 5, c = i & 31;
        float4 v = ((const float4*)Wt)[h * 32 + c];
        *(float4*)&swt[h][c * 4] = v;
    }
    for (int i = tid; i < 16 * 32; i += 256) {
        int r = i >> 5, c = i & 31;
        float4 v = make_float4(0.f, 0.f, 0.f, 0.f);
        if (t0 + r < n_tissue) v = ((const float4*)tissue)[(size_t)(t0 + r) * 32 + c];
        *(float4*)&st[r][c * 4] = v;
    }
    __syncthreads();

    #pragma unroll
    for (int j = 0; j < 4; j++) {
        int o = tid + j * 256;
        int tl = o >> 6, h = o & 63;
        if (t0 + tl >= n_tissue) continue;
        float acc = bt[h] + bc[h];
        #pragma unroll 8
        for (int c = 0; c < 32; c++) {
            float4 w = *(const float4*)&swt[h][c * 4];
            float4 x = *(const float4*)&st[tl][c * 4];
            acc += w.x * x.x + w.y * x.y + w.z * x.z + w.w * x.w;
        }
        g_tkb[(size_t)(t0 + tl) * HID + h] = acc;
    }
}

// ---------------------------------------------------------------------------
__device__ __forceinline__ unsigned f2tf32(float x) {
    unsigned r;
    asm("cvt.rna.tf32.f32 %0, %1;" : "=r"(r) : "f"(x));
    return r;
}
__device__ __forceinline__ float tanh_ap(float x) {
    float y;
    asm("tanh.approx.f32 %0, %1;" : "=f"(y) : "f"(x));
    return y;
}
__device__ __forceinline__ void cp_async16(void* sdst, const void* gsrc, bool pred) {
    unsigned s = (unsigned)__cvta_generic_to_shared(sdst);
    int sz = pred ? 16 : 0;
    asm volatile("cp.async.cg.shared.global [%0], [%1], 16, %2;\n"
                 :: "r"(s), "l"(gsrc), "r"(sz));
}
__device__ __forceinline__ void cp_async4(void* sdst, const void* gsrc, bool pred) {
    unsigned s = (unsigned)__cvta_generic_to_shared(sdst);
    int sz = pred ? 4 : 0;
    asm volatile("cp.async.ca.shared.global [%0], [%1], 4, %2;\n"
                 :: "r"(s), "l"(gsrc), "r"(sz));
}
__device__ __forceinline__ void cp_commit() {
    asm volatile("cp.async.commit_group;\n" ::: "memory");
}
__device__ __forceinline__ void cp_wait1() {
    asm volatile("cp.async.wait_group 1;\n" ::: "memory");
}
__device__ __forceinline__ void ldm_x4(unsigned* r, unsigned saddr) {
    asm volatile("ldmatrix.sync.aligned.m8n8.x4.shared.b16 {%0,%1,%2,%3}, [%4];"
                 : "=r"(r[0]), "=r"(r[1]), "=r"(r[2]), "=r"(r[3])
                 : "r"(saddr));
}

extern __shared__ float smem[];

// ---------------------------------------------------------------------------
// Kernel B: persistent, double-buffered; 32-row tiles; 3 CTAs/SM
// Warp grid: 2 m-tiles (16 rows) x 4 n-quarters (16 cols)
// ---------------------------------------------------------------------------
__global__ __launch_bounds__(256, 3)
void fuse_kernel(const float* __restrict__ cellf,
                 const float* __restrict__ tissuef,
                 const int* __restrict__ c2t,
                 const float* __restrict__ Wc,
                 const float* __restrict__ attnw,
                 float* __restrict__ out,
                 int n_cell, int ntiles) {
    float*    sx    = smem;                              // 2 buffers, 32*132
    unsigned* swc   = (unsigned*)(sx + 2 * TILE * SXS);  // 64*132 tf32 bits
    int*      stid  = (int*)(swc + 64 * SWS);            // 2 buffers, 32 each
    float*    spart = (float*)(stid + 2 * TILE);         // 4 * 32 partials
    float*    sattn = spart + 4 * TILE;                  // 64

    int tid = threadIdx.x;

    // ---- one-time staging: Wc (tf32, RN) + attn weights ----
    for (int i = tid; i < 64 * 32; i += 256) {
        int r = i >> 5, c = i & 31;
        float4 v = ((const float4*)Wc)[r * 32 + c];
        uint4 w;
        w.x = f2tf32(v.x); w.y = f2tf32(v.y); w.z = f2tf32(v.z); w.w = f2tf32(v.w);
        *(uint4*)&swc[r * SWS + c * 4] = w;
    }
    if (tid < 64) sattn[tid] = attnw[tid];

    int wid = tid >> 5, lane = tid & 31;
    int gid = lane >> 2, tig = lane & 3;
    int wm = wid & 1, wn = wid >> 1;     // 2 m-tiles x 4 n-quarters
    int m0 = wm * 16;
    int rlo = m0 + gid, rhi = m0 + gid + 8;
    int h0 = wn * 16;

    // ldmatrix lane addressing: mat = lane/8, row-in-mat = lane%8
    int lml = lane & 7, lmm = lane >> 3;
    unsigned sx_u  = (unsigned)__cvta_generic_to_shared(sx);
    unsigned swc_u = (unsigned)__cvta_generic_to_shared(swc);
    // A mats: {rows m0..+7 | m0+8..+15} x {k-cols +0..3 | +4..7}
    unsigned a_off = ((unsigned)((m0 + (lmm & 1) * 8 + lml) * SXS + (lmm >> 1) * 4)) * 4u;
    // B mats: rows h0+lml, k-col groups {0,4,8,12} by mat (two kk per x4)
    unsigned b_off = swc_u + ((unsigned)((h0 + lml) * SWS + lmm * 4)) * 4u;

    // ---- tile issue helper ----
    auto issue_tile = [&](int t, int buf) {
        float* dst = sx + buf * TILE * SXS;
        int base = t * TILE;
        #pragma unroll
        for (int j = 0; j < 4; j++) {
            int i = tid + j * 256;
            int r = i >> 5, c = i & 31;
            int row = base + r;
            bool ok = row < n_cell;
            int rowc = ok ? row : (n_cell - 1);
            cp_async16(&dst[r * SXS + c * 4],
                       cellf + (size_t)rowc * DIM + c * 4, ok);
        }
        if (tid < TILE) {
            int row = base + tid;
            bool ok = row < n_cell;
            int rowc = ok ? row : 0;
            cp_async4(&stid[buf * TILE + tid], c2t + rowc, ok);
        }
    };

    int t0 = blockIdx.x;
    if (t0 < ntiles) issue_tile(t0, 0);
    cp_commit();

    int it = 0;
    for (int t = t0; t < ntiles; t += gridDim.x, it++) {
        int buf = it & 1;
        int tn = t + gridDim.x;
        if (tn < ntiles) issue_tile(tn, buf ^ 1);
        cp_commit();
        cp_wait1();            // tile t resident
        __syncthreads();       // covers one-time Wc staging on iter 0

        int base = t * TILE;
        float* bx = sx + buf * TILE * SXS;
        int* bt_ = stid + buf * TILE;
        unsigned abase = sx_u + (unsigned)(buf * TILE * SXS) * 4u + a_off;

        // ---- init accumulators from gathered tissue keys (bias pre-folded) ----
        float acc[2][4];
        {
            int tlo = bt_[rlo] & (MAX_TISSUE - 1);
            int thi = bt_[rhi] & (MAX_TISSUE - 1);
            const float2* klo = (const float2*)&g_tkb[(size_t)tlo * HID];
            const float2* khi = (const float2*)&g_tkb[(size_t)thi * HID];
            #pragma unroll
            for (int nt = 0; nt < 2; nt++) {
                float2 a = klo[wn * 8 + nt * 4 + tig];
                float2 b = khi[wn * 8 + nt * 4 + tig];
                acc[nt][0] = a.x; acc[nt][1] = a.y;
                acc[nt][2] = b.x; acc[nt][3] = b.y;
            }
        }

        // ---- Q += X @ Wc^T via ldmatrix + mma.sync m16n8k8 tf32 ----
        #pragma unroll
        for (int p = 0; p < 8; p++) {
            unsigned a0[4], a1[4];
            ldm_x4(a0, abase + (unsigned)(p * 64));        // kk = 2p
            ldm_x4(a1, abase + (unsigned)(p * 64 + 32));   // kk = 2p+1
            #pragma unroll
            for (int nt = 0; nt < 2; nt++) {
                unsigned b[4];  // b[0],b[1]: kk=2p ; b[2],b[3]: kk=2p+1
                ldm_x4(b, b_off + (unsigned)(nt * 8 * SWS) * 4u + (unsigned)(p * 64));
                asm volatile(
                    "mma.sync.aligned.m16n8k8.row.col.f32.tf32.tf32.f32 "
                    "{%0,%1,%2,%3}, {%4,%5,%6,%7}, {%8,%9}, {%0,%1,%2,%3};\n"
                    : "+f"(acc[nt][0]), "+f"(acc[nt][1]),
                      "+f"(acc[nt][2]), "+f"(acc[nt][3])
                    : "r"(a0[0]), "r"(a0[1]), "r"(a0[2]), "r"(a0[3]),
                      "r"(b[0]), "r"(b[1]));
                asm volatile(
                    "mma.sync.aligned.m16n8k8.row.col.f32.tf32.tf32.f32 "
                    "{%0,%1,%2,%3}, {%4,%5,%6,%7}, {%8,%9}, {%0,%1,%2,%3};\n"
                    : "+f"(acc[nt][0]), "+f"(acc[nt][1]),
                      "+f"(acc[nt][2]), "+f"(acc[nt][3])
                    : "r"(a1[0]), "r"(a1[1]), "r"(a1[2]), "r"(a1[3]),
                      "r"(b[2]), "r"(b[3]));
            }
        }

        // ---- partial score = attn . tanh(acc) over this warp's 16 cols ----
        float p0 = 0.f, p1 = 0.f;
        #pragma unroll
        for (int nt = 0; nt < 2; nt++) {
            float aw0 = sattn[h0 + nt * 8 + tig * 2];
            float aw1 = sattn[h0 + nt * 8 + tig * 2 + 1];
            p0 += aw0 * tanh_ap(acc[nt][0]) + aw1 * tanh_ap(acc[nt][1]);
            p1 += aw0 * tanh_ap(acc[nt][2]) + aw1 * tanh_ap(acc[nt][3]);
        }
        p0 += __shfl_xor_sync(0xffffffffu, p0, 1);
        p0 += __shfl_xor_sync(0xffffffffu, p0, 2);
        p1 += __shfl_xor_sync(0xffffffffu, p1, 1);
        p1 += __shfl_xor_sync(0xffffffffu, p1, 2);
        if (tig == 0) {
            spart[wn * TILE + rlo] = p0;
            spart[wn * TILE + rhi] = p1;
        }
        __syncthreads();

        // ---- epilogue: gate computed inline, out = x + tissue[t]*gate ----
        #pragma unroll
        for (int j = 0; j < 4; j++) {
            int i = tid + j * 256;
            int r = i >> 5, c = i & 31;
            int row = base + r;
            if (row >= n_cell) continue;
            float s = spart[r] + spart[TILE + r]
                    + spart[2 * TILE + r] + spart[3 * TILE + r];
            float g = __fdividef(1.f, 1.f + __expf(-s));
            float4 xv = *(const float4*)&bx[r * SXS + c * 4];
            int tt = bt_[r];
            float4 tv = ((const float4*)tissuef)[(size_t)tt * 32 + c];
            float4 o;
            o.x = fmaf(tv.x, g, xv.x);
            o.y = fmaf(tv.y, g, xv.y);
            o.z = fmaf(tv.z, g, xv.z);
            o.w = fmaf(tv.w, g, xv.w);
            ((float4*)out)[(size_t)row * 32 + c] = o;
        }
        __syncthreads();   // buffer reusable next-next iteration
    }
}

// ---------------------------------------------------------------------------
extern "C" void kernel_launch(void* const* d_in, const int* in_sizes, int n_in,
                              void* d_out, int out_size) {
    const float* cellf   = (const float*)d_in[0];
    const float* tissuef = (const float*)d_in[1];
    const int*   c2t     = (const int*)d_in[2];
    const float* Wt      = (const float*)d_in[3];
    const float* bt      = (const float*)d_in[4];
    const float* Wc      = (const float*)d_in[5];
    const float* bc      = (const float*)d_in[6];
    const float* attnw   = (const float*)d_in[7];
    float* out = (float*)d_out;

    int n_cell   = in_sizes[0] / DIM;
    int n_tissue = in_sizes[1] / DIM;
    int ntiles   = (n_cell + TILE - 1) / TILE;

    tissue_proj_kernel<<<(n_tissue + 15) / 16, 256>>>(tissuef, Wt, bt, bc, n_tissue);

    int dev = 0, sms = 148;
    cudaGetDevice(&dev);
    cudaDeviceGetAttribute(&sms, cudaDevAttrMultiProcessorCount, dev);

    size_t shmem_bytes =
        (size_t)(2 * TILE * SXS + 64 * SWS) * 4   // X bufs + Wc
        + (2 * TILE) * 4                           // stid
        + (4 * TILE) * 4                           // spart
        + 64 * 4;                                  // sattn
    cudaFuncSetAttribute(fuse_kernel,
                         cudaFuncAttributeMaxDynamicSharedMemorySize,
                         (int)shmem_bytes);
    int grid = 3 * sms;
    if (grid > ntiles) grid = ntiles;
    fuse_kernel<<<grid, 256, shmem_bytes>>>(cellf, tissuef, c2t, Wc, attnw,
                                            out, n_cell, ntiles);
}